// round 10
// baseline (speedup 1.0000x reference)
#include <cuda_runtime.h>
#include <cuda_fp16.h>
#include <cstdint>
#include <math.h>

// ---------------------------------------------------------------------------
// MoE expert-choice via mma.sync fp16 (f32 accum). sm_103 ptxas lacks tcgen05.
// route -> top-512/expert -> gather(fp16) -> GEMM1+SiLU -> GEMM2 -> scatter
// GEMM: CTA tile 128x128, 256 threads, 2 CTAs/SM, K-slab 64, 3-stage cp.async.
// GEMM2 split-K x2 (wave balance). Graph-parallel prep/zero branches.
// ---------------------------------------------------------------------------

#define NE     8
#define DM     1024
#define DF     4096
#define SEQ    2048
#define BATCH  4
#define TOPK   512
#define NPAIR  32

__device__ float  g_probs[BATCH * SEQ * NE];
__device__ int    g_idx[NPAIR * TOPK];
__device__ float  g_gate[NPAIR * TOPK];
__device__ __align__(128) __half g_xg16[(size_t)NPAIR * TOPK * DM];   //  33MB
__device__ __align__(128) __half g_h16 [(size_t)NPAIR * TOPK * DF];   // 134MB
__device__ __align__(128) __half g_w1h [(size_t)NE * DF * DM];        //  67MB
__device__ __align__(128) __half g_w2h [(size_t)NE * DM * DF];        //  67MB

#define CP16(dst, src)  asm volatile("cp.async.cg.shared.global [%0], [%1], 16;" :: "r"(dst), "l"(src))
#define CP_COMMIT()     asm volatile("cp.async.commit_group;" ::: "memory")

__device__ __forceinline__ uint32_t smem_u32(const void* p) {
    uint32_t a;
    asm("{ .reg .u64 t; cvta.to.shared.u64 t, %1; cvt.u32.u64 %0, t; }" : "=r"(a) : "l"(p));
    return a;
}

#define LDSM4(r0, r1, r2, r3, addr) \
    asm volatile("ldmatrix.sync.aligned.m8n8.x4.shared.b16 {%0,%1,%2,%3}, [%4];" \
        : "=r"(r0), "=r"(r1), "=r"(r2), "=r"(r3) : "r"(addr))

__device__ __forceinline__ void mma_f16(float* c, const uint32_t* a, const uint32_t* b) {
    asm volatile(
        "mma.sync.aligned.m16n8k16.row.col.f32.f16.f16.f32 "
        "{%0,%1,%2,%3}, {%4,%5,%6,%7}, {%8,%9}, {%0,%1,%2,%3};"
        : "+f"(c[0]), "+f"(c[1]), "+f"(c[2]), "+f"(c[3])
        : "r"(a[0]), "r"(a[1]), "r"(a[2]), "r"(a[3]), "r"(b[0]), "r"(b[1]));
}

// ---------------------------------------------------------------------------
// 1) Routing softmax (fp32 exact). 16 tokens/block, warp-per-token x2,
//    choice staged in smem, float4 everywhere.
// ---------------------------------------------------------------------------
#define RT_TOK 16
__global__ void __launch_bounds__(256) k_route(const float* __restrict__ x,
                                               const float* __restrict__ choice) {
    __shared__ float cs[NE][DM];                 // 32KB
    const int t = threadIdx.x, w = t >> 5, lane = t & 31;

    for (int i = t; i < NE * DM / 4; i += 256)
        ((float4*)&cs[0][0])[i] = ((const float4*)choice)[i];
    __syncthreads();

#pragma unroll
    for (int tt = 0; tt < 2; tt++) {
        const int token = blockIdx.x * RT_TOK + w * 2 + tt;
        const float4* xr = (const float4*)(x + (size_t)token * DM);

        float acc[NE];
#pragma unroll
        for (int e = 0; e < NE; e++) acc[e] = 0.f;

#pragma unroll
        for (int i = 0; i < DM / 128; i++) {     // 8 iters
            const float4 xv = xr[lane + i * 32];
#pragma unroll
            for (int e = 0; e < NE; e++) {
                const float4 cv = ((const float4*)&cs[e][0])[lane + i * 32];
                acc[e] = fmaf(xv.x, cv.x, acc[e]);
                acc[e] = fmaf(xv.y, cv.y, acc[e]);
                acc[e] = fmaf(xv.z, cv.z, acc[e]);
                acc[e] = fmaf(xv.w, cv.w, acc[e]);
            }
        }
#pragma unroll
        for (int e = 0; e < NE; e++)
#pragma unroll
            for (int o = 16; o > 0; o >>= 1)
                acc[e] += __shfl_xor_sync(0xffffffffu, acc[e], o);

        if (lane == 0) {
            float mx = -1e30f;
#pragma unroll
            for (int e = 0; e < NE; e++) mx = fmaxf(mx, acc[e]);
            float s = 0.f;
#pragma unroll
            for (int e = 0; e < NE; e++) { acc[e] = expf(acc[e] - mx); s += acc[e]; }
            const float inv = 1.f / s;
#pragma unroll
            for (int e = 0; e < NE; e++) g_probs[token * NE + e] = acc[e] * inv;
        }
    }
}

// ---------------------------------------------------------------------------
// 2) Exact top-K per (batch, expert)
// ---------------------------------------------------------------------------
__global__ void k_topk() {
    const int pair = blockIdx.x, b = pair >> 3, e = pair & 7;
    const int t = threadIdx.x;               // 1024
    __shared__ unsigned keys[SEQ];
    __shared__ int s_cnt;

    for (int s = t; s < SEQ; s += blockDim.x) {
        unsigned bits = __float_as_uint(g_probs[((size_t)b * SEQ + s) * NE + e]);
        keys[s] = (bits & 0x80000000u) ? ~bits : (bits | 0x80000000u);
    }
    __syncthreads();

    unsigned lo = 0u, hi = 0xFFFFFFFFu;
    while (lo < hi) {
        const unsigned mid = lo + ((hi - lo) >> 1) + 1u;
        if (t == 0) s_cnt = 0;
        __syncthreads();
        int c = 0;
        for (int s = t; s < SEQ; s += blockDim.x) c += (keys[s] >= mid);
#pragma unroll
        for (int o = 16; o > 0; o >>= 1) c += __shfl_down_sync(0xffffffffu, c, o);
        if ((t & 31) == 0 && c) atomicAdd(&s_cnt, c);
        __syncthreads();
        const int cnt = s_cnt;
        __syncthreads();
        if (cnt >= TOPK) lo = mid; else hi = mid - 1u;
    }
    const unsigned T = lo;

    if (t == 0) s_cnt = 0;
    __syncthreads();
    for (int s = t; s < SEQ; s += blockDim.x) {
        if (keys[s] > T) {
            const int p = atomicAdd(&s_cnt, 1);
            g_idx[pair * TOPK + p]  = s;
            g_gate[pair * TOPK + p] = g_probs[((size_t)b * SEQ + s) * NE + e];
        }
    }
    __syncthreads();
    for (int s = t; s < SEQ; s += blockDim.x) {
        if (keys[s] == T) {
            const int p = atomicAdd(&s_cnt, 1);
            if (p < TOPK) {
                g_idx[pair * TOPK + p]  = s;
                g_gate[pair * TOPK + p] = g_probs[((size_t)b * SEQ + s) * NE + e];
            }
        }
    }
}

// ---------------------------------------------------------------------------
// 3) Weight prep: RN-round fp32 -> fp16 (split per matrix for graph overlap)
// ---------------------------------------------------------------------------
__global__ void k_prep1(const float* __restrict__ w1) {
    const size_t i = (size_t)blockIdx.x * blockDim.x + threadIdx.x;
    const size_t N4 = (size_t)NE * DF * DM / 4;
    if (i >= N4) return;
    float4 a = ((const float4*)w1)[i];
    __half2 a0 = __floats2half2_rn(a.x, a.y);
    __half2 a1 = __floats2half2_rn(a.z, a.w);
    uint2 ua;
    ua.x = *reinterpret_cast<unsigned*>(&a0);
    ua.y = *reinterpret_cast<unsigned*>(&a1);
    ((uint2*)g_w1h)[i] = ua;
}
__global__ void k_prep2(const float* __restrict__ w2) {
    const size_t i = (size_t)blockIdx.x * blockDim.x + threadIdx.x;
    const size_t N4 = (size_t)NE * DF * DM / 4;
    if (i >= N4) return;
    float4 c = ((const float4*)w2)[i];
    __half2 c0 = __floats2half2_rn(c.x, c.y);
    __half2 c1 = __floats2half2_rn(c.z, c.w);
    uint2 uc;
    uc.x = *reinterpret_cast<unsigned*>(&c0);
    uc.y = *reinterpret_cast<unsigned*>(&c1);
    ((uint2*)g_w2h)[i] = uc;
}

// ---------------------------------------------------------------------------
// 4) Gather selected tokens, fp32 -> fp16
// ---------------------------------------------------------------------------
__global__ void k_gather(const float* __restrict__ x) {
    const int row = blockIdx.x;
    const int pair = row >> 9, b = pair >> 3;
    const int tok = g_idx[pair * TOPK + (row & 511)];
    const float4* src = (const float4*)(x + ((size_t)b * SEQ + tok) * DM);
    uint2* dst = (uint2*)(g_xg16 + (size_t)row * DM);
    for (int i = threadIdx.x; i < DM / 4; i += 128) {
        float4 v = src[i];
        __half2 h0 = __floats2half2_rn(v.x, v.y);
        __half2 h1 = __floats2half2_rn(v.z, v.w);
        uint2 u;
        u.x = *reinterpret_cast<unsigned*>(&h0);
        u.y = *reinterpret_cast<unsigned*>(&h1);
        dst[i] = u;
    }
}

// ---------------------------------------------------------------------------
// 5) fp16 mma.sync GEMM. CTA tile 128x128, 8 warps (4x2), warp tile 32x64,
//    K-slab 64, 3-stage cp.async, ldmatrix, SPAD=72 conflict-free.
//    KSPL-way split-K: blockIdx.z = pair*KSPL + part; epilogue atomics make
//    split-K free for G2.
// ---------------------------------------------------------------------------
#define SPAD        72
#define A_BYTES     (128 * SPAD * 2)     // 18432
#define STAGE_BYTES (2 * A_BYTES)        // 36864
#define NSTAGE      3
#define SMEM_MMA    (NSTAGE * STAGE_BYTES)  // 110592 (2 CTAs/SM = 216KB)

template<int K, int KSPL, bool G1>
__global__ void __launch_bounds__(256, 2) k_mma(const __half* __restrict__ Aall,
                                                const __half* __restrict__ Ball,
                                                void* __restrict__ outp) {
    constexpr int KLEN = K / KSPL;
    constexpr int NS = KLEN / 64;
    extern __shared__ __align__(16) char smem[];
    const uint32_t sb = smem_u32(smem);

    const int tid  = threadIdx.x;
    const int wid  = tid >> 5, lane = tid & 31;
    const int wm   = wid >> 1, wn = wid & 1;
    const int g    = lane >> 2, tg = lane & 3;
    const int mi   = lane >> 3, r8 = lane & 7;

    const int zz    = blockIdx.z;
    const int pair  = zz / KSPL, part = zz % KSPL;
    const int e = pair & 7, b = pair >> 3;
    const int mBase = blockIdx.y * 128;
    const int nBase = blockIdx.x * 128;

    const __half* Abase = Aall + ((size_t)pair * TOPK + mBase) * K + (size_t)part * KLEN;
    const __half* Bbase = Ball + (size_t)e * DF * DM + (size_t)nBase * K + (size_t)part * KLEN;

    uint32_t aoff[2], boff[4];
#pragma unroll
    for (int mt = 0; mt < 2; mt++)
        aoff[mt] = ((wm * 32 + mt * 16 + (mi & 1) * 8 + r8) * SPAD + (mi >> 1) * 8) * 2;
#pragma unroll
    for (int np = 0; np < 4; np++)
        boff[np] = ((wn * 64 + np * 16 + (mi >> 1) * 8 + r8) * SPAD + (mi & 1) * 8) * 2;

    auto load_slab = [&](int slab, int buf) {
        const char* Ap = (const char*)(Abase) + (size_t)slab * 128;
        const char* Bp = (const char*)(Bbase) + (size_t)slab * 128;
        const uint32_t sA = sb + buf * STAGE_BYTES;
        const uint32_t sB = sA + A_BYTES;
#pragma unroll
        for (int i = 0; i < 4; i++) {
            const int id = tid + i * 256;        // 0..1023
            const int row = id >> 3, c16 = id & 7;
            const uint32_t off = row * (SPAD * 2) + c16 * 16;
            CP16(sA + off, Ap + (size_t)row * (K * 2) + c16 * 16);
            CP16(sB + off, Bp + (size_t)row * (K * 2) + c16 * 16);
        }
    };

    float acc[2][8][4];
#pragma unroll
    for (int mt = 0; mt < 2; mt++)
#pragma unroll
        for (int nt = 0; nt < 8; nt++)
#pragma unroll
            for (int f = 0; f < 4; f++) acc[mt][nt][f] = 0.f;

    load_slab(0, 0); CP_COMMIT();
    load_slab(1, 1); CP_COMMIT();

#pragma unroll 1
    for (int s = 0; s < NS; s++) {
        asm volatile("cp.async.wait_group %0;" :: "n"(NSTAGE - 2) : "memory");
        __syncthreads();
        if (s + 2 < NS) { load_slab(s + 2, (s + 2) % NSTAGE); }
        CP_COMMIT();

        const uint32_t sA = sb + (s % NSTAGE) * STAGE_BYTES;
        const uint32_t sB = sA + A_BYTES;
#pragma unroll
        for (int ks = 0; ks < 4; ks++) {
            const uint32_t kofs = ks * 32;
            uint32_t af[2][4];
#pragma unroll
            for (int mt = 0; mt < 2; mt++)
                LDSM4(af[mt][0], af[mt][1], af[mt][2], af[mt][3], sA + aoff[mt] + kofs);
            uint32_t bf[8][2];
#pragma unroll
            for (int np = 0; np < 4; np++)
                LDSM4(bf[2 * np][0], bf[2 * np][1], bf[2 * np + 1][0], bf[2 * np + 1][1],
                      sB + boff[np] + kofs);
#pragma unroll
            for (int mt = 0; mt < 2; mt++)
#pragma unroll
                for (int nt = 0; nt < 8; nt++)
                    mma_f16(acc[mt][nt], af[mt], bf[nt]);
        }
    }

    // ---- epilogue ----
    if (G1) {
        __half* hout = (__half*)outp;
#pragma unroll
        for (int mt = 0; mt < 2; mt++) {
            const int r0 = mBase + wm * 32 + mt * 16 + g;
#pragma unroll
            for (int nt = 0; nt < 8; nt++) {
                const int col = nBase + wn * 64 + nt * 8 + 2 * tg;
                const float* a = acc[mt][nt];
                __half2 lo = __floats2half2_rn(a[0] / (1.f + __expf(-a[0])),
                                               a[1] / (1.f + __expf(-a[1])));
                __half2 hi = __floats2half2_rn(a[2] / (1.f + __expf(-a[2])),
                                               a[3] / (1.f + __expf(-a[3])));
                *(unsigned*)(hout + ((size_t)pair * TOPK + r0) * DF + col)     = *reinterpret_cast<unsigned*>(&lo);
                *(unsigned*)(hout + ((size_t)pair * TOPK + r0 + 8) * DF + col) = *reinterpret_cast<unsigned*>(&hi);
            }
        }
    } else {
        float* out = (float*)outp;
#pragma unroll
        for (int mt = 0; mt < 2; mt++) {
            const int m0 = mBase + wm * 32 + mt * 16 + g;
            const int tok0 = g_idx[pair * TOPK + m0];
            const int tok1 = g_idx[pair * TOPK + m0 + 8];
            const float g0 = g_gate[pair * TOPK + m0];
            const float g1 = g_gate[pair * TOPK + m0 + 8];
            float* d0 = out + ((size_t)b * SEQ + tok0) * DM;
            float* d1 = out + ((size_t)b * SEQ + tok1) * DM;
#pragma unroll
            for (int nt = 0; nt < 8; nt++) {
                const int col = nBase + wn * 64 + nt * 8 + 2 * tg;
                const float* a = acc[mt][nt];
                atomicAdd(d0 + col,     g0 * a[0]);
                atomicAdd(d0 + col + 1, g0 * a[1]);
                atomicAdd(d1 + col,     g1 * a[2]);
                atomicAdd(d1 + col + 1, g1 * a[3]);
            }
        }
    }
}

// ---------------------------------------------------------------------------
// 6) Zero output (poisoned before timing)
// ---------------------------------------------------------------------------
__global__ void k_zero(float* __restrict__ out, int n4) {
    const int i = blockIdx.x * blockDim.x + threadIdx.x;
    if (i < n4) ((float4*)out)[i] = make_float4(0.f, 0.f, 0.f, 0.f);
}

// ---------------------------------------------------------------------------
extern "C" void kernel_launch(void* const* d_in, const int* in_sizes, int n_in,
                              void* d_out, int out_size) {
    const float* x      = (const float*)d_in[0];
    const float* choice = (const float*)d_in[1];
    const float* w1     = (const float*)d_in[2];
    const float* w2     = (const float*)d_in[3];
    float* out = (float*)d_out;

    // One-time setup (runs on the uncaptured correctness call; no device alloc).
    static cudaStream_t s1, s2;
    static cudaEvent_t ev0, ev1, ev2;
    static int inited = 0;
    if (!inited) {
        cudaFuncSetAttribute((const void*)k_mma<DM, 1, true>,  cudaFuncAttributeMaxDynamicSharedMemorySize, SMEM_MMA);
        cudaFuncSetAttribute((const void*)k_mma<DF, 2, false>, cudaFuncAttributeMaxDynamicSharedMemorySize, SMEM_MMA);
        cudaStreamCreateWithFlags(&s1, cudaStreamNonBlocking);
        cudaStreamCreateWithFlags(&s2, cudaStreamNonBlocking);
        cudaEventCreateWithFlags(&ev0, cudaEventDisableTiming);
        cudaEventCreateWithFlags(&ev1, cudaEventDisableTiming);
        cudaEventCreateWithFlags(&ev2, cudaEventDisableTiming);
        inited = 1;
    }

    __half* xg_p;  cudaGetSymbolAddress((void**)&xg_p,  g_xg16);
    __half* h_p;   cudaGetSymbolAddress((void**)&h_p,   g_h16);
    __half* w1h_p; cudaGetSymbolAddress((void**)&w1h_p, g_w1h);
    __half* w2h_p; cudaGetSymbolAddress((void**)&w2h_p, g_w2h);

    const unsigned PREP_BLKS = (unsigned)(((size_t)NE * DF * DM / 4 + 255) / 256);
    const int n4 = BATCH * SEQ * DM / 4;

    // Fork side branches off the main stream.
    cudaEventRecord(ev0, 0);
    cudaStreamWaitEvent(s1, ev0, 0);
    cudaStreamWaitEvent(s2, ev0, 0);

    // Branch s1: w1 conversion (needed by GEMM1).
    k_prep1<<<PREP_BLKS, 256, 0, s1>>>(w1);
    cudaEventRecord(ev1, s1);

    // Branch s2: w2 conversion + output zeroing (needed by GEMM2).
    k_prep2<<<PREP_BLKS, 256, 0, s2>>>(w2);
    k_zero<<<(n4 + 255) / 256, 256, 0, s2>>>(out, n4);
    cudaEventRecord(ev2, s2);

    // Main branch: routing -> topk -> gather.
    k_route<<<(BATCH * SEQ) / RT_TOK, 256>>>(x, choice);
    k_topk<<<NPAIR, 1024>>>();
    k_gather<<<NPAIR * TOPK, 128>>>(x);

    // Join w1 branch, run GEMM1: [512 x 4096], K=1024 per pair.
    cudaStreamWaitEvent(0, ev1, 0);
    k_mma<DM, 1, true><<<dim3(DF / 128, TOPK / 128, NPAIR), 256, SMEM_MMA>>>(xg_p, w1h_p, h_p);

    // Join w2+zero branch, run GEMM2: [512 x 1024], K=4096, split-K x2.
    cudaStreamWaitEvent(0, ev2, 0);
    k_mma<DF, 2, false><<<dim3(DM / 128, TOPK / 128, NPAIR * 2), 256, SMEM_MMA>>>(h_p, w2h_p, out);
}

// round 13
// speedup vs baseline: 1.0235x; 1.0235x over previous
#include <cuda_runtime.h>
#include <cuda_fp16.h>
#include <cstdint>
#include <math.h>

// ---------------------------------------------------------------------------
// MoE expert-choice via mma.sync fp16 (f32 accum). sm_103 ptxas lacks tcgen05.
// route -> top-512/expert -> gather(fp16) -> GEMM1+SiLU -> GEMM2 -> scatter
// GEMM: CTA tile 128x128, 256 threads, 2 CTAs/SM, K-slab 64, 3-stage cp.async.
// G2 scatter uses red.global.add.v2.f32. Graph-parallel prep/zero branches.
// ---------------------------------------------------------------------------

#define NE     8
#define DM     1024
#define DF     4096
#define SEQ    2048
#define BATCH  4
#define TOPK   512
#define NPAIR  32

__device__ float  g_probs[BATCH * SEQ * NE];
__device__ int    g_idx[NPAIR * TOPK];
__device__ float  g_gate[NPAIR * TOPK];
__device__ __align__(128) __half g_xg16[(size_t)NPAIR * TOPK * DM];   //  33MB
__device__ __align__(128) __half g_h16 [(size_t)NPAIR * TOPK * DF];   // 134MB
__device__ __align__(128) __half g_w1h [(size_t)NE * DF * DM];        //  67MB
__device__ __align__(128) __half g_w2h [(size_t)NE * DM * DF];        //  67MB

#define CP16(dst, src)  asm volatile("cp.async.cg.shared.global [%0], [%1], 16;" :: "r"(dst), "l"(src))
#define CP_COMMIT()     asm volatile("cp.async.commit_group;" ::: "memory")

__device__ __forceinline__ uint32_t smem_u32(const void* p) {
    uint32_t a;
    asm("{ .reg .u64 t; cvta.to.shared.u64 t, %1; cvt.u32.u64 %0, t; }" : "=r"(a) : "l"(p));
    return a;
}

#define LDSM4(r0, r1, r2, r3, addr) \
    asm volatile("ldmatrix.sync.aligned.m8n8.x4.shared.b16 {%0,%1,%2,%3}, [%4];" \
        : "=r"(r0), "=r"(r1), "=r"(r2), "=r"(r3) : "r"(addr))

__device__ __forceinline__ void mma_f16(float* c, const uint32_t* a, const uint32_t* b) {
    asm volatile(
        "mma.sync.aligned.m16n8k16.row.col.f32.f16.f16.f32 "
        "{%0,%1,%2,%3}, {%4,%5,%6,%7}, {%8,%9}, {%0,%1,%2,%3};"
        : "+f"(c[0]), "+f"(c[1]), "+f"(c[2]), "+f"(c[3])
        : "r"(a[0]), "r"(a[1]), "r"(a[2]), "r"(a[3]), "r"(b[0]), "r"(b[1]));
}

__device__ __forceinline__ void red_add_v2(float* addr, float a, float b) {
    asm volatile("red.global.add.v2.f32 [%0], {%1, %2};"
                 :: "l"(addr), "f"(a), "f"(b) : "memory");
}

// ---------------------------------------------------------------------------
// 1) Routing softmax (fp32 exact — selection must match reference)
// ---------------------------------------------------------------------------
__global__ void k_route(const float* __restrict__ x, const float* __restrict__ choice) {
    const int token = blockIdx.x;
    const float* xr = x + (size_t)token * DM;
    const int t = threadIdx.x;               // 128

    float acc[NE];
#pragma unroll
    for (int e = 0; e < NE; e++) acc[e] = 0.f;
    for (int d = t; d < DM; d += 128) {
        const float xv = xr[d];
#pragma unroll
        for (int e = 0; e < NE; e++) acc[e] = fmaf(xv, choice[e * DM + d], acc[e]);
    }
    __shared__ float red[NE][128];
#pragma unroll
    for (int e = 0; e < NE; e++) red[e][t] = acc[e];
    __syncthreads();
    for (int ofs = 64; ofs > 0; ofs >>= 1) {
        if (t < ofs) {
#pragma unroll
            for (int e = 0; e < NE; e++) red[e][t] += red[e][t + ofs];
        }
        __syncthreads();
    }
    if (t == 0) {
        float l[NE], mx = -1e30f;
#pragma unroll
        for (int e = 0; e < NE; e++) { l[e] = red[e][0]; mx = fmaxf(mx, l[e]); }
        float s = 0.f;
#pragma unroll
        for (int e = 0; e < NE; e++) { l[e] = expf(l[e] - mx); s += l[e]; }
        const float inv = 1.f / s;
#pragma unroll
        for (int e = 0; e < NE; e++) g_probs[token * NE + e] = l[e] * inv;
    }
}

// ---------------------------------------------------------------------------
// 2) Exact top-K per (batch, expert)
// ---------------------------------------------------------------------------
__global__ void k_topk() {
    const int pair = blockIdx.x, b = pair >> 3, e = pair & 7;
    const int t = threadIdx.x;               // 1024
    __shared__ unsigned keys[SEQ];
    __shared__ int s_cnt;

    for (int s = t; s < SEQ; s += blockDim.x) {
        unsigned bits = __float_as_uint(g_probs[((size_t)b * SEQ + s) * NE + e]);
        keys[s] = (bits & 0x80000000u) ? ~bits : (bits | 0x80000000u);
    }
    __syncthreads();

    unsigned lo = 0u, hi = 0xFFFFFFFFu;
    while (lo < hi) {
        const unsigned mid = lo + ((hi - lo) >> 1) + 1u;
        if (t == 0) s_cnt = 0;
        __syncthreads();
        int c = 0;
        for (int s = t; s < SEQ; s += blockDim.x) c += (keys[s] >= mid);
#pragma unroll
        for (int o = 16; o > 0; o >>= 1) c += __shfl_down_sync(0xffffffffu, c, o);
        if ((t & 31) == 0 && c) atomicAdd(&s_cnt, c);
        __syncthreads();
        const int cnt = s_cnt;
        __syncthreads();
        if (cnt >= TOPK) lo = mid; else hi = mid - 1u;
    }
    const unsigned T = lo;

    if (t == 0) s_cnt = 0;
    __syncthreads();
    for (int s = t; s < SEQ; s += blockDim.x) {
        if (keys[s] > T) {
            const int p = atomicAdd(&s_cnt, 1);
            g_idx[pair * TOPK + p]  = s;
            g_gate[pair * TOPK + p] = g_probs[((size_t)b * SEQ + s) * NE + e];
        }
    }
    __syncthreads();
    for (int s = t; s < SEQ; s += blockDim.x) {
        if (keys[s] == T) {
            const int p = atomicAdd(&s_cnt, 1);
            if (p < TOPK) {
                g_idx[pair * TOPK + p]  = s;
                g_gate[pair * TOPK + p] = g_probs[((size_t)b * SEQ + s) * NE + e];
            }
        }
    }
}

// ---------------------------------------------------------------------------
// 3) Weight prep: RN-round fp32 -> fp16 (split per matrix for graph overlap)
// ---------------------------------------------------------------------------
__global__ void k_prep1(const float* __restrict__ w1) {
    const size_t i = (size_t)blockIdx.x * blockDim.x + threadIdx.x;
    const size_t N4 = (size_t)NE * DF * DM / 4;
    if (i >= N4) return;
    float4 a = ((const float4*)w1)[i];
    __half2 a0 = __floats2half2_rn(a.x, a.y);
    __half2 a1 = __floats2half2_rn(a.z, a.w);
    uint2 ua;
    ua.x = *reinterpret_cast<unsigned*>(&a0);
    ua.y = *reinterpret_cast<unsigned*>(&a1);
    ((uint2*)g_w1h)[i] = ua;
}
__global__ void k_prep2(const float* __restrict__ w2) {
    const size_t i = (size_t)blockIdx.x * blockDim.x + threadIdx.x;
    const size_t N4 = (size_t)NE * DF * DM / 4;
    if (i >= N4) return;
    float4 c = ((const float4*)w2)[i];
    __half2 c0 = __floats2half2_rn(c.x, c.y);
    __half2 c1 = __floats2half2_rn(c.z, c.w);
    uint2 uc;
    uc.x = *reinterpret_cast<unsigned*>(&c0);
    uc.y = *reinterpret_cast<unsigned*>(&c1);
    ((uint2*)g_w2h)[i] = uc;
}

// ---------------------------------------------------------------------------
// 4) Gather selected tokens, fp32 -> fp16
// ---------------------------------------------------------------------------
__global__ void k_gather(const float* __restrict__ x) {
    const int row = blockIdx.x;
    const int pair = row >> 9, b = pair >> 3;
    const int tok = g_idx[pair * TOPK + (row & 511)];
    const float4* src = (const float4*)(x + ((size_t)b * SEQ + tok) * DM);
    uint2* dst = (uint2*)(g_xg16 + (size_t)row * DM);
    for (int i = threadIdx.x; i < DM / 4; i += 128) {
        float4 v = src[i];
        __half2 h0 = __floats2half2_rn(v.x, v.y);
        __half2 h1 = __floats2half2_rn(v.z, v.w);
        uint2 u;
        u.x = *reinterpret_cast<unsigned*>(&h0);
        u.y = *reinterpret_cast<unsigned*>(&h1);
        dst[i] = u;
    }
}

// ---------------------------------------------------------------------------
// 5) fp16 mma.sync GEMM. CTA tile 128x128, 8 warps (4x2), warp tile 32x64,
//    K-slab 64 halves, 3-stage cp.async pipeline (one barrier per slab),
//    ldmatrix fragment loads. Smem rows padded to 72 halves (144B):
//    conflict-free ldmatrix and cp.async stores.
// ---------------------------------------------------------------------------
#define SPAD        72
#define A_BYTES     (128 * SPAD * 2)     // 18432
#define STAGE_BYTES (2 * A_BYTES)        // 36864
#define NSTAGE      3
#define SMEM_MMA    (NSTAGE * STAGE_BYTES)  // 110592 (2 CTAs/SM = 216KB <= 228KB)

template<int K, bool G1>
__global__ void __launch_bounds__(256, 2) k_mma(const __half* __restrict__ Aall,
                                                const __half* __restrict__ Ball,
                                                void* __restrict__ outp) {
    constexpr int NS = K / 64;
    extern __shared__ __align__(16) char smem[];
    const uint32_t sb = smem_u32(smem);

    const int tid  = threadIdx.x;
    const int wid  = tid >> 5, lane = tid & 31;
    const int wm   = wid >> 1, wn = wid & 1;
    const int g    = lane >> 2, tg = lane & 3;
    const int mi   = lane >> 3, r8 = lane & 7;

    const int pair  = blockIdx.z, e = pair & 7, b = pair >> 3;
    const int mBase = blockIdx.y * 128;
    const int nBase = blockIdx.x * 128;

    const __half* Abase = Aall + ((size_t)pair * TOPK + mBase) * K;
    const __half* Bbase = Ball + (size_t)e * DF * DM + (size_t)nBase * K;

    // ldmatrix per-thread relative byte offsets (within a stage)
    uint32_t aoff[2], boff[4];
#pragma unroll
    for (int mt = 0; mt < 2; mt++)
        aoff[mt] = ((wm * 32 + mt * 16 + (mi & 1) * 8 + r8) * SPAD + (mi >> 1) * 8) * 2;
#pragma unroll
    for (int np = 0; np < 4; np++)
        boff[np] = ((wn * 64 + np * 16 + (mi >> 1) * 8 + r8) * SPAD + (mi & 1) * 8) * 2;

    // Loader: A 128 rows x 8 x 16B chunks, B same (K-slab 64 halves = 128B/row).
    auto load_slab = [&](int slab, int buf) {
        const char* Ap = (const char*)(Abase) + (size_t)slab * 128;
        const char* Bp = (const char*)(Bbase) + (size_t)slab * 128;
        const uint32_t sA = sb + buf * STAGE_BYTES;
        const uint32_t sB = sA + A_BYTES;
#pragma unroll
        for (int i = 0; i < 4; i++) {
            const int id = tid + i * 256;        // 0..1023
            const int row = id >> 3, c16 = id & 7;
            const uint32_t off = row * (SPAD * 2) + c16 * 16;
            CP16(sA + off, Ap + (size_t)row * (K * 2) + c16 * 16);
            CP16(sB + off, Bp + (size_t)row * (K * 2) + c16 * 16);
        }
    };

    float acc[2][8][4];
#pragma unroll
    for (int mt = 0; mt < 2; mt++)
#pragma unroll
        for (int nt = 0; nt < 8; nt++)
#pragma unroll
            for (int f = 0; f < 4; f++) acc[mt][nt][f] = 0.f;

    load_slab(0, 0); CP_COMMIT();
    load_slab(1, 1); CP_COMMIT();

#pragma unroll 1
    for (int s = 0; s < NS; s++) {
        asm volatile("cp.async.wait_group %0;" :: "n"(NSTAGE - 2) : "memory");
        __syncthreads();
        // Prefetch slab s+2 into the buffer consumed at slab s-1.
        if (s + 2 < NS) { load_slab(s + 2, (s + 2) % NSTAGE); }
        CP_COMMIT();

        const uint32_t sA = sb + (s % NSTAGE) * STAGE_BYTES;
        const uint32_t sB = sA + A_BYTES;
#pragma unroll
        for (int ks = 0; ks < 4; ks++) {
            const uint32_t kofs = ks * 32;       // 16 halves
            uint32_t af[2][4];
#pragma unroll
            for (int mt = 0; mt < 2; mt++)
                LDSM4(af[mt][0], af[mt][1], af[mt][2], af[mt][3], sA + aoff[mt] + kofs);
            uint32_t bf[8][2];
#pragma unroll
            for (int np = 0; np < 4; np++)
                LDSM4(bf[2 * np][0], bf[2 * np][1], bf[2 * np + 1][0], bf[2 * np + 1][1],
                      sB + boff[np] + kofs);
#pragma unroll
            for (int mt = 0; mt < 2; mt++)
#pragma unroll
                for (int nt = 0; nt < 8; nt++)
                    mma_f16(acc[mt][nt], af[mt], bf[nt]);
        }
    }

    // ---- epilogue ----
    if (G1) {
        __half* hout = (__half*)outp;
#pragma unroll
        for (int mt = 0; mt < 2; mt++) {
            const int r0 = mBase + wm * 32 + mt * 16 + g;
#pragma unroll
            for (int nt = 0; nt < 8; nt++) {
                const int col = nBase + wn * 64 + nt * 8 + 2 * tg;
                const float* a = acc[mt][nt];
                __half2 lo = __floats2half2_rn(a[0] / (1.f + __expf(-a[0])),
                                               a[1] / (1.f + __expf(-a[1])));
                __half2 hi = __floats2half2_rn(a[2] / (1.f + __expf(-a[2])),
                                               a[3] / (1.f + __expf(-a[3])));
                *(unsigned*)(hout + ((size_t)pair * TOPK + r0) * DF + col)     = *reinterpret_cast<unsigned*>(&lo);
                *(unsigned*)(hout + ((size_t)pair * TOPK + r0 + 8) * DF + col) = *reinterpret_cast<unsigned*>(&hi);
            }
        }
    } else {
        float* out = (float*)outp;
#pragma unroll
        for (int mt = 0; mt < 2; mt++) {
            const int m0 = mBase + wm * 32 + mt * 16 + g;
            const int tok0 = g_idx[pair * TOPK + m0];
            const int tok1 = g_idx[pair * TOPK + m0 + 8];
            const float g0 = g_gate[pair * TOPK + m0];
            const float g1 = g_gate[pair * TOPK + m0 + 8];
            float* d0 = out + ((size_t)b * SEQ + tok0) * DM;
            float* d1 = out + ((size_t)b * SEQ + tok1) * DM;
#pragma unroll
            for (int nt = 0; nt < 8; nt++) {
                const int col = nBase + wn * 64 + nt * 8 + 2 * tg;  // 8B-aligned
                const float* a = acc[mt][nt];
                red_add_v2(d0 + col, g0 * a[0], g0 * a[1]);
                red_add_v2(d1 + col, g1 * a[2], g1 * a[3]);
            }
        }
    }
}

// ---------------------------------------------------------------------------
// 6) Zero output (poisoned before timing)
// ---------------------------------------------------------------------------
__global__ void k_zero(float* __restrict__ out, int n4) {
    const int i = blockIdx.x * blockDim.x + threadIdx.x;
    if (i < n4) ((float4*)out)[i] = make_float4(0.f, 0.f, 0.f, 0.f);
}

// ---------------------------------------------------------------------------
extern "C" void kernel_launch(void* const* d_in, const int* in_sizes, int n_in,
                              void* d_out, int out_size) {
    const float* x      = (const float*)d_in[0];
    const float* choice = (const float*)d_in[1];
    const float* w1     = (const float*)d_in[2];
    const float* w2     = (const float*)d_in[3];
    float* out = (float*)d_out;

    // One-time setup (runs on the uncaptured correctness call; no device alloc).
    static cudaStream_t s1, s2;
    static cudaEvent_t ev0, ev1, ev2;
    static int inited = 0;
    if (!inited) {
        cudaFuncSetAttribute(k_mma<DM, true>,  cudaFuncAttributeMaxDynamicSharedMemorySize, SMEM_MMA);
        cudaFuncSetAttribute(k_mma<DF, false>, cudaFuncAttributeMaxDynamicSharedMemorySize, SMEM_MMA);
        cudaStreamCreateWithFlags(&s1, cudaStreamNonBlocking);
        cudaStreamCreateWithFlags(&s2, cudaStreamNonBlocking);
        cudaEventCreateWithFlags(&ev0, cudaEventDisableTiming);
        cudaEventCreateWithFlags(&ev1, cudaEventDisableTiming);
        cudaEventCreateWithFlags(&ev2, cudaEventDisableTiming);
        inited = 1;
    }

    __half* xg_p;  cudaGetSymbolAddress((void**)&xg_p,  g_xg16);
    __half* h_p;   cudaGetSymbolAddress((void**)&h_p,   g_h16);
    __half* w1h_p; cudaGetSymbolAddress((void**)&w1h_p, g_w1h);
    __half* w2h_p; cudaGetSymbolAddress((void**)&w2h_p, g_w2h);

    const unsigned PREP_BLKS = (unsigned)(((size_t)NE * DF * DM / 4 + 255) / 256);
    const int n4 = BATCH * SEQ * DM / 4;

    // Fork side branches off the main stream.
    cudaEventRecord(ev0, 0);
    cudaStreamWaitEvent(s1, ev0, 0);
    cudaStreamWaitEvent(s2, ev0, 0);

    // Branch s1: w1 conversion (needed by GEMM1).
    k_prep1<<<PREP_BLKS, 256, 0, s1>>>(w1);
    cudaEventRecord(ev1, s1);

    // Branch s2: w2 conversion + output zeroing (needed by GEMM2).
    k_prep2<<<PREP_BLKS, 256, 0, s2>>>(w2);
    k_zero<<<(n4 + 255) / 256, 256, 0, s2>>>(out, n4);
    cudaEventRecord(ev2, s2);

    // Main branch: routing -> topk -> gather.
    k_route<<<BATCH * SEQ, 128>>>(x, choice);
    k_topk<<<NPAIR, 1024>>>();
    k_gather<<<NPAIR * TOPK, 128>>>(x);

    // Join w1 branch, run GEMM1: [512 x 4096], K=1024 per pair.
    cudaStreamWaitEvent(0, ev1, 0);
    k_mma<DM, true><<<dim3(DF / 128, TOPK / 128, NPAIR), 256, SMEM_MMA>>>(xg_p, w1h_p, h_p);

    // Join w2+zero branch, run GEMM2: [512 x 1024], K=4096 per pair.
    cudaStreamWaitEvent(0, ev2, 0);
    k_mma<DF, false><<<dim3(DM / 128, TOPK / 128, NPAIR), 256, SMEM_MMA>>>(h_p, w2h_p, out);
}

// round 15
// speedup vs baseline: 1.0302x; 1.0066x over previous
#include <cuda_runtime.h>
#include <cuda_fp16.h>
#include <cstdint>
#include <math.h>

// ---------------------------------------------------------------------------
// MoE expert-choice via mma.sync fp16 (f32 accum). sm_103 ptxas lacks tcgen05.
// route -> top-512/expert -> gather(fp16) -> GEMM1+SiLU -> GEMM2 -> scatter
// GEMM: CTA tile 128x128, 256 threads, 2 CTAs/SM, K-slab 64, 3-stage cp.async.
// Expert-major z-order (same-expert pairs adjacent -> L2 weight reuse).
// G2 scatter uses red.global.add.v2.f32. Graph-parallel prep/zero branches.
// ---------------------------------------------------------------------------

#define NE     8
#define DM     1024
#define DF     4096
#define SEQ    2048
#define BATCH  4
#define TOPK   512
#define NPAIR  32

__device__ float  g_probs[BATCH * SEQ * NE];
__device__ int    g_idx[NPAIR * TOPK];
__device__ float  g_gate[NPAIR * TOPK];
__device__ __align__(128) __half g_xg16[(size_t)NPAIR * TOPK * DM];   //  33MB
__device__ __align__(128) __half g_h16 [(size_t)NPAIR * TOPK * DF];   // 134MB
__device__ __align__(128) __half g_w1h [(size_t)NE * DF * DM];        //  67MB
__device__ __align__(128) __half g_w2h [(size_t)NE * DM * DF];        //  67MB

#define CP16(dst, src)  asm volatile("cp.async.cg.shared.global [%0], [%1], 16;" :: "r"(dst), "l"(src))
#define CP_COMMIT()     asm volatile("cp.async.commit_group;" ::: "memory")

__device__ __forceinline__ uint32_t smem_u32(const void* p) {
    uint32_t a;
    asm("{ .reg .u64 t; cvta.to.shared.u64 t, %1; cvt.u32.u64 %0, t; }" : "=r"(a) : "l"(p));
    return a;
}

#define LDSM4(r0, r1, r2, r3, addr) \
    asm volatile("ldmatrix.sync.aligned.m8n8.x4.shared.b16 {%0,%1,%2,%3}, [%4];" \
        : "=r"(r0), "=r"(r1), "=r"(r2), "=r"(r3) : "r"(addr))

__device__ __forceinline__ void mma_f16(float* c, const uint32_t* a, const uint32_t* b) {
    asm volatile(
        "mma.sync.aligned.m16n8k16.row.col.f32.f16.f16.f32 "
        "{%0,%1,%2,%3}, {%4,%5,%6,%7}, {%8,%9}, {%0,%1,%2,%3};"
        : "+f"(c[0]), "+f"(c[1]), "+f"(c[2]), "+f"(c[3])
        : "r"(a[0]), "r"(a[1]), "r"(a[2]), "r"(a[3]), "r"(b[0]), "r"(b[1]));
}

__device__ __forceinline__ void red_add_v2(float* addr, float a, float b) {
    asm volatile("red.global.add.v2.f32 [%0], {%1, %2};"
                 :: "l"(addr), "f"(a), "f"(b) : "memory");
}

// ---------------------------------------------------------------------------
// 1) Routing softmax (fp32 exact — selection must match reference)
// ---------------------------------------------------------------------------
__global__ void k_route(const float* __restrict__ x, const float* __restrict__ choice) {
    const int token = blockIdx.x;
    const float* xr = x + (size_t)token * DM;
    const int t = threadIdx.x;               // 128

    float acc[NE];
#pragma unroll
    for (int e = 0; e < NE; e++) acc[e] = 0.f;
    for (int d = t; d < DM; d += 128) {
        const float xv = xr[d];
#pragma unroll
        for (int e = 0; e < NE; e++) acc[e] = fmaf(xv, choice[e * DM + d], acc[e]);
    }
    __shared__ float red[NE][128];
#pragma unroll
    for (int e = 0; e < NE; e++) red[e][t] = acc[e];
    __syncthreads();
    for (int ofs = 64; ofs > 0; ofs >>= 1) {
        if (t < ofs) {
#pragma unroll
            for (int e = 0; e < NE; e++) red[e][t] += red[e][t + ofs];
        }
        __syncthreads();
    }
    if (t == 0) {
        float l[NE], mx = -1e30f;
#pragma unroll
        for (int e = 0; e < NE; e++) { l[e] = red[e][0]; mx = fmaxf(mx, l[e]); }
        float s = 0.f;
#pragma unroll
        for (int e = 0; e < NE; e++) { l[e] = expf(l[e] - mx); s += l[e]; }
        const float inv = 1.f / s;
#pragma unroll
        for (int e = 0; e < NE; e++) g_probs[token * NE + e] = l[e] * inv;
    }
}

// ---------------------------------------------------------------------------
// 2) Exact top-K per (batch, expert)
// ---------------------------------------------------------------------------
__global__ void k_topk() {
    const int pair = blockIdx.x, b = pair >> 3, e = pair & 7;
    const int t = threadIdx.x;               // 1024
    __shared__ unsigned keys[SEQ];
    __shared__ int s_cnt;

    for (int s = t; s < SEQ; s += blockDim.x) {
        unsigned bits = __float_as_uint(g_probs[((size_t)b * SEQ + s) * NE + e]);
        keys[s] = (bits & 0x80000000u) ? ~bits : (bits | 0x80000000u);
    }
    __syncthreads();

    unsigned lo = 0u, hi = 0xFFFFFFFFu;
    while (lo < hi) {
        const unsigned mid = lo + ((hi - lo) >> 1) + 1u;
        if (t == 0) s_cnt = 0;
        __syncthreads();
        int c = 0;
        for (int s = t; s < SEQ; s += blockDim.x) c += (keys[s] >= mid);
#pragma unroll
        for (int o = 16; o > 0; o >>= 1) c += __shfl_down_sync(0xffffffffu, c, o);
        if ((t & 31) == 0 && c) atomicAdd(&s_cnt, c);
        __syncthreads();
        const int cnt = s_cnt;
        __syncthreads();
        if (cnt >= TOPK) lo = mid; else hi = mid - 1u;
    }
    const unsigned T = lo;

    if (t == 0) s_cnt = 0;
    __syncthreads();
    for (int s = t; s < SEQ; s += blockDim.x) {
        if (keys[s] > T) {
            const int p = atomicAdd(&s_cnt, 1);
            g_idx[pair * TOPK + p]  = s;
            g_gate[pair * TOPK + p] = g_probs[((size_t)b * SEQ + s) * NE + e];
        }
    }
    __syncthreads();
    for (int s = t; s < SEQ; s += blockDim.x) {
        if (keys[s] == T) {
            const int p = atomicAdd(&s_cnt, 1);
            if (p < TOPK) {
                g_idx[pair * TOPK + p]  = s;
                g_gate[pair * TOPK + p] = g_probs[((size_t)b * SEQ + s) * NE + e];
            }
        }
    }
}

// ---------------------------------------------------------------------------
// 3) Weight prep: RN-round fp32 -> fp16 (split per matrix for graph overlap)
// ---------------------------------------------------------------------------
__global__ void k_prep1(const float* __restrict__ w1) {
    const size_t i = (size_t)blockIdx.x * blockDim.x + threadIdx.x;
    const size_t N4 = (size_t)NE * DF * DM / 4;
    if (i >= N4) return;
    float4 a = ((const float4*)w1)[i];
    __half2 a0 = __floats2half2_rn(a.x, a.y);
    __half2 a1 = __floats2half2_rn(a.z, a.w);
    uint2 ua;
    ua.x = *reinterpret_cast<unsigned*>(&a0);
    ua.y = *reinterpret_cast<unsigned*>(&a1);
    ((uint2*)g_w1h)[i] = ua;
}
__global__ void k_prep2(const float* __restrict__ w2) {
    const size_t i = (size_t)blockIdx.x * blockDim.x + threadIdx.x;
    const size_t N4 = (size_t)NE * DF * DM / 4;
    if (i >= N4) return;
    float4 c = ((const float4*)w2)[i];
    __half2 c0 = __floats2half2_rn(c.x, c.y);
    __half2 c1 = __floats2half2_rn(c.z, c.w);
    uint2 uc;
    uc.x = *reinterpret_cast<unsigned*>(&c0);
    uc.y = *reinterpret_cast<unsigned*>(&c1);
    ((uint2*)g_w2h)[i] = uc;
}

// ---------------------------------------------------------------------------
// 4) Gather selected tokens, fp32 -> fp16
// ---------------------------------------------------------------------------
__global__ void k_gather(const float* __restrict__ x) {
    const int row = blockIdx.x;
    const int pair = row >> 9, b = pair >> 3;
    const int tok = g_idx[pair * TOPK + (row & 511)];
    const float4* src = (const float4*)(x + ((size_t)b * SEQ + tok) * DM);
    uint2* dst = (uint2*)(g_xg16 + (size_t)row * DM);
    for (int i = threadIdx.x; i < DM / 4; i += 128) {
        float4 v = src[i];
        __half2 h0 = __floats2half2_rn(v.x, v.y);
        __half2 h1 = __floats2half2_rn(v.z, v.w);
        uint2 u;
        u.x = *reinterpret_cast<unsigned*>(&h0);
        u.y = *reinterpret_cast<unsigned*>(&h1);
        dst[i] = u;
    }
}

// ---------------------------------------------------------------------------
// 5) fp16 mma.sync GEMM. CTA tile 128x128, 8 warps (4x2), warp tile 32x64,
//    K-slab 64 halves, 3-stage cp.async pipeline (one barrier per slab),
//    ldmatrix fragment loads, SPAD=72 conflict-free.
//    Expert-major z: e = z>>2, b = z&3 so the 4 same-expert pairs are
//    adjacent in wave order and share the expert's weight slab in L2.
// ---------------------------------------------------------------------------
#define SPAD        72
#define A_BYTES     (128 * SPAD * 2)     // 18432
#define STAGE_BYTES (2 * A_BYTES)        // 36864
#define NSTAGE      3
#define SMEM_MMA    (NSTAGE * STAGE_BYTES)  // 110592 (2 CTAs/SM = 216KB <= 228KB)

template<int K, bool G1>
__global__ void __launch_bounds__(256, 2) k_mma(const __half* __restrict__ Aall,
                                                const __half* __restrict__ Ball,
                                                void* __restrict__ outp) {
    constexpr int NS = K / 64;
    extern __shared__ __align__(16) char smem[];
    const uint32_t sb = smem_u32(smem);

    const int tid  = threadIdx.x;
    const int wid  = tid >> 5, lane = tid & 31;
    const int wm   = wid >> 1, wn = wid & 1;
    const int g    = lane >> 2, tg = lane & 3;
    const int mi   = lane >> 3, r8 = lane & 7;

    // Expert-major ordering: adjacent z-slices share the expert weight slab.
    const int e = blockIdx.z >> 2, b = blockIdx.z & 3;
    const int pair = b * NE + e;                 // data layout index
    const int mBase = blockIdx.y * 128;
    const int nBase = blockIdx.x * 128;

    const __half* Abase = Aall + ((size_t)pair * TOPK + mBase) * K;
    const __half* Bbase = Ball + (size_t)e * DF * DM + (size_t)nBase * K;

    // ldmatrix per-thread relative byte offsets (within a stage)
    uint32_t aoff[2], boff[4];
#pragma unroll
    for (int mt = 0; mt < 2; mt++)
        aoff[mt] = ((wm * 32 + mt * 16 + (mi & 1) * 8 + r8) * SPAD + (mi >> 1) * 8) * 2;
#pragma unroll
    for (int np = 0; np < 4; np++)
        boff[np] = ((wn * 64 + np * 16 + (mi >> 1) * 8 + r8) * SPAD + (mi & 1) * 8) * 2;

    // Loader: A 128 rows x 8 x 16B chunks, B same (K-slab 64 halves = 128B/row).
    auto load_slab = [&](int slab, int buf) {
        const char* Ap = (const char*)(Abase) + (size_t)slab * 128;
        const char* Bp = (const char*)(Bbase) + (size_t)slab * 128;
        const uint32_t sA = sb + buf * STAGE_BYTES;
        const uint32_t sB = sA + A_BYTES;
#pragma unroll
        for (int i = 0; i < 4; i++) {
            const int id = tid + i * 256;        // 0..1023
            const int row = id >> 3, c16 = id & 7;
            const uint32_t off = row * (SPAD * 2) + c16 * 16;
            CP16(sA + off, Ap + (size_t)row * (K * 2) + c16 * 16);
            CP16(sB + off, Bp + (size_t)row * (K * 2) + c16 * 16);
        }
    };

    float acc[2][8][4];
#pragma unroll
    for (int mt = 0; mt < 2; mt++)
#pragma unroll
        for (int nt = 0; nt < 8; nt++)
#pragma unroll
            for (int f = 0; f < 4; f++) acc[mt][nt][f] = 0.f;

    load_slab(0, 0); CP_COMMIT();
    load_slab(1, 1); CP_COMMIT();

#pragma unroll 1
    for (int s = 0; s < NS; s++) {
        asm volatile("cp.async.wait_group %0;" :: "n"(NSTAGE - 2) : "memory");
        __syncthreads();
        // Prefetch slab s+2 into the buffer consumed at slab s-1.
        if (s + 2 < NS) { load_slab(s + 2, (s + 2) % NSTAGE); }
        CP_COMMIT();

        const uint32_t sA = sb + (s % NSTAGE) * STAGE_BYTES;
        const uint32_t sB = sA + A_BYTES;
#pragma unroll
        for (int ks = 0; ks < 4; ks++) {
            const uint32_t kofs = ks * 32;       // 16 halves
            uint32_t af[2][4];
#pragma unroll
            for (int mt = 0; mt < 2; mt++)
                LDSM4(af[mt][0], af[mt][1], af[mt][2], af[mt][3], sA + aoff[mt] + kofs);
            uint32_t bf[8][2];
#pragma unroll
            for (int np = 0; np < 4; np++)
                LDSM4(bf[2 * np][0], bf[2 * np][1], bf[2 * np + 1][0], bf[2 * np + 1][1],
                      sB + boff[np] + kofs);
#pragma unroll
            for (int mt = 0; mt < 2; mt++)
#pragma unroll
                for (int nt = 0; nt < 8; nt++)
                    mma_f16(acc[mt][nt], af[mt], bf[nt]);
        }
    }

    // ---- epilogue ----
    if (G1) {
        __half* hout = (__half*)outp;
#pragma unroll
        for (int mt = 0; mt < 2; mt++) {
            const int r0 = mBase + wm * 32 + mt * 16 + g;
#pragma unroll
            for (int nt = 0; nt < 8; nt++) {
                const int col = nBase + wn * 64 + nt * 8 + 2 * tg;
                const float* a = acc[mt][nt];
                __half2 lo = __floats2half2_rn(a[0] / (1.f + __expf(-a[0])),
                                               a[1] / (1.f + __expf(-a[1])));
                __half2 hi = __floats2half2_rn(a[2] / (1.f + __expf(-a[2])),
                                               a[3] / (1.f + __expf(-a[3])));
                *(unsigned*)(hout + ((size_t)pair * TOPK + r0) * DF + col)     = *reinterpret_cast<unsigned*>(&lo);
                *(unsigned*)(hout + ((size_t)pair * TOPK + r0 + 8) * DF + col) = *reinterpret_cast<unsigned*>(&hi);
            }
        }
    } else {
        float* out = (float*)outp;
#pragma unroll
        for (int mt = 0; mt < 2; mt++) {
            const int m0 = mBase + wm * 32 + mt * 16 + g;
            const int tok0 = g_idx[pair * TOPK + m0];
            const int tok1 = g_idx[pair * TOPK + m0 + 8];
            const float g0 = g_gate[pair * TOPK + m0];
            const float g1 = g_gate[pair * TOPK + m0 + 8];
            float* d0 = out + ((size_t)b * SEQ + tok0) * DM;
            float* d1 = out + ((size_t)b * SEQ + tok1) * DM;
#pragma unroll
            for (int nt = 0; nt < 8; nt++) {
                const int col = nBase + wn * 64 + nt * 8 + 2 * tg;  // 8B-aligned
                const float* a = acc[mt][nt];
                red_add_v2(d0 + col, g0 * a[0], g0 * a[1]);
                red_add_v2(d1 + col, g1 * a[2], g1 * a[3]);
            }
        }
    }
}

// ---------------------------------------------------------------------------
// 6) Zero output (poisoned before timing)
// ---------------------------------------------------------------------------
__global__ void k_zero(float* __restrict__ out, int n4) {
    const int i = blockIdx.x * blockDim.x + threadIdx.x;
    if (i < n4) ((float4*)out)[i] = make_float4(0.f, 0.f, 0.f, 0.f);
}

// ---------------------------------------------------------------------------
extern "C" void kernel_launch(void* const* d_in, const int* in_sizes, int n_in,
                              void* d_out, int out_size) {
    const float* x      = (const float*)d_in[0];
    const float* choice = (const float*)d_in[1];
    const float* w1     = (const float*)d_in[2];
    const float* w2     = (const float*)d_in[3];
    float* out = (float*)d_out;

    // One-time setup (runs on the uncaptured correctness call; no device alloc).
    static cudaStream_t s1, s2;
    static cudaEvent_t ev0, ev1, ev2;
    static int inited = 0;
    if (!inited) {
        cudaFuncSetAttribute(k_mma<DM, true>,  cudaFuncAttributeMaxDynamicSharedMemorySize, SMEM_MMA);
        cudaFuncSetAttribute(k_mma<DF, false>, cudaFuncAttributeMaxDynamicSharedMemorySize, SMEM_MMA);
        cudaStreamCreateWithFlags(&s1, cudaStreamNonBlocking);
        cudaStreamCreateWithFlags(&s2, cudaStreamNonBlocking);
        cudaEventCreateWithFlags(&ev0, cudaEventDisableTiming);
        cudaEventCreateWithFlags(&ev1, cudaEventDisableTiming);
        cudaEventCreateWithFlags(&ev2, cudaEventDisableTiming);
        inited = 1;
    }

    __half* xg_p;  cudaGetSymbolAddress((void**)&xg_p,  g_xg16);
    __half* h_p;   cudaGetSymbolAddress((void**)&h_p,   g_h16);
    __half* w1h_p; cudaGetSymbolAddress((void**)&w1h_p, g_w1h);
    __half* w2h_p; cudaGetSymbolAddress((void**)&w2h_p, g_w2h);

    const unsigned PREP_BLKS = (unsigned)(((size_t)NE * DF * DM / 4 + 255) / 256);
    const int n4 = BATCH * SEQ * DM / 4;

    // Fork side branches off the main stream.
    cudaEventRecord(ev0, 0);
    cudaStreamWaitEvent(s1, ev0, 0);
    cudaStreamWaitEvent(s2, ev0, 0);

    // Branch s1: w1 conversion (needed by GEMM1).
    k_prep1<<<PREP_BLKS, 256, 0, s1>>>(w1);
    cudaEventRecord(ev1, s1);

    // Branch s2: w2 conversion + output zeroing (needed by GEMM2).
    k_prep2<<<PREP_BLKS, 256, 0, s2>>>(w2);
    k_zero<<<(n4 + 255) / 256, 256, 0, s2>>>(out, n4);
    cudaEventRecord(ev2, s2);

    // Main branch: routing -> topk -> gather.
    k_route<<<BATCH * SEQ, 128>>>(x, choice);
    k_topk<<<NPAIR, 1024>>>();
    k_gather<<<NPAIR * TOPK, 128>>>(x);

    // Join w1 branch, run GEMM1: [512 x 4096], K=1024 per pair.
    cudaStreamWaitEvent(0, ev1, 0);
    k_mma<DM, true><<<dim3(DF / 128, TOPK / 128, NPAIR), 256, SMEM_MMA>>>(xg_p, w1h_p, h_p);

    // Join w2+zero branch, run GEMM2: [512 x 1024], K=4096 per pair.
    cudaStreamWaitEvent(0, ev2, 0);
    k_mma<DF, false><<<dim3(DM / 128, TOPK / 128, NPAIR), 256, SMEM_MMA>>>(h_p, w2h_p, out);
}

// round 16
// speedup vs baseline: 1.0522x; 1.0213x over previous
#include <cuda_runtime.h>
#include <cuda_fp16.h>
#include <cstdint>
#include <math.h>

// ---------------------------------------------------------------------------
// MoE expert-choice via mma.sync fp16 (f32 accum). sm_103 ptxas lacks tcgen05.
// x->fp16 -> route -> top-512/expert -> GEMM1(direct gather)+SiLU -> GEMM2
// -> gated scatter. GEMM: 128x128 tile, 256 thr, 2 CTAs/SM, K-slab 64,
// 3-stage cp.async, expert-major z. Graph-parallel prep/zero branches.
// ---------------------------------------------------------------------------

#define NE     8
#define DM     1024
#define DF     4096
#define SEQ    2048
#define BATCH  4
#define TOPK   512
#define NPAIR  32

__device__ float  g_probs[BATCH * SEQ * NE];
__device__ int    g_idx[NPAIR * TOPK];
__device__ float  g_gate[NPAIR * TOPK];
__device__ __align__(128) __half g_x16 [(size_t)BATCH * SEQ * DM];    //  17MB
__device__ __align__(128) __half g_h16 [(size_t)NPAIR * TOPK * DF];   // 134MB
__device__ __align__(128) __half g_w1h [(size_t)NE * DF * DM];        //  67MB
__device__ __align__(128) __half g_w2h [(size_t)NE * DM * DF];        //  67MB

#define CP16(dst, src)  asm volatile("cp.async.cg.shared.global [%0], [%1], 16;" :: "r"(dst), "l"(src))
#define CP_COMMIT()     asm volatile("cp.async.commit_group;" ::: "memory")

__device__ __forceinline__ uint32_t smem_u32(const void* p) {
    uint32_t a;
    asm("{ .reg .u64 t; cvta.to.shared.u64 t, %1; cvt.u32.u64 %0, t; }" : "=r"(a) : "l"(p));
    return a;
}

#define LDSM4(r0, r1, r2, r3, addr) \
    asm volatile("ldmatrix.sync.aligned.m8n8.x4.shared.b16 {%0,%1,%2,%3}, [%4];" \
        : "=r"(r0), "=r"(r1), "=r"(r2), "=r"(r3) : "r"(addr))

__device__ __forceinline__ void mma_f16(float* c, const uint32_t* a, const uint32_t* b) {
    asm volatile(
        "mma.sync.aligned.m16n8k16.row.col.f32.f16.f16.f32 "
        "{%0,%1,%2,%3}, {%4,%5,%6,%7}, {%8,%9}, {%0,%1,%2,%3};"
        : "+f"(c[0]), "+f"(c[1]), "+f"(c[2]), "+f"(c[3])
        : "r"(a[0]), "r"(a[1]), "r"(a[2]), "r"(a[3]), "r"(b[0]), "r"(b[1]));
}

__device__ __forceinline__ void red_add_v2(float* addr, float a, float b) {
    asm volatile("red.global.add.v2.f32 [%0], {%1, %2};"
                 :: "l"(addr), "f"(a), "f"(b) : "memory");
}

// ---------------------------------------------------------------------------
// 0) Convert full x to fp16 (no routing dependency).
// ---------------------------------------------------------------------------
__global__ void k_x16(const float* __restrict__ x) {
    const size_t i = (size_t)blockIdx.x * blockDim.x + threadIdx.x;
    const size_t N4 = (size_t)BATCH * SEQ * DM / 4;
    if (i >= N4) return;
    float4 v = ((const float4*)x)[i];
    __half2 h0 = __floats2half2_rn(v.x, v.y);
    __half2 h1 = __floats2half2_rn(v.z, v.w);
    uint2 u;
    u.x = *reinterpret_cast<unsigned*>(&h0);
    u.y = *reinterpret_cast<unsigned*>(&h1);
    ((uint2*)g_x16)[i] = u;
}

// ---------------------------------------------------------------------------
// 1) Routing softmax (fp32). Warp per token, choice staged in smem, float4.
// ---------------------------------------------------------------------------
__global__ void __launch_bounds__(256) k_route(const float* __restrict__ x,
                                               const float* __restrict__ choice) {
    __shared__ float cs[NE * DM];                // 32KB
    const int t = threadIdx.x, w = t >> 5, lane = t & 31;

    for (int i = t; i < NE * DM / 4; i += 256)
        ((float4*)cs)[i] = ((const float4*)choice)[i];
    __syncthreads();

    const int token = blockIdx.x * 8 + w;
    const float4* xr = (const float4*)(x + (size_t)token * DM);

    float acc[NE];
#pragma unroll
    for (int e = 0; e < NE; e++) acc[e] = 0.f;

#pragma unroll
    for (int i = 0; i < DM / 128; i++) {         // 8 iters
        const float4 xv = xr[lane + i * 32];
#pragma unroll
        for (int e = 0; e < NE; e++) {
            const float4 cv = ((const float4*)(cs + e * DM))[lane + i * 32];
            acc[e] = fmaf(xv.x, cv.x, acc[e]);
            acc[e] = fmaf(xv.y, cv.y, acc[e]);
            acc[e] = fmaf(xv.z, cv.z, acc[e]);
            acc[e] = fmaf(xv.w, cv.w, acc[e]);
        }
    }
#pragma unroll
    for (int e = 0; e < NE; e++)
#pragma unroll
        for (int o = 16; o > 0; o >>= 1)
            acc[e] += __shfl_xor_sync(0xffffffffu, acc[e], o);

    if (lane == 0) {
        float mx = -1e30f;
#pragma unroll
        for (int e = 0; e < NE; e++) mx = fmaxf(mx, acc[e]);
        float s = 0.f;
#pragma unroll
        for (int e = 0; e < NE; e++) { acc[e] = expf(acc[e] - mx); s += acc[e]; }
        const float inv = 1.f / s;
#pragma unroll
        for (int e = 0; e < NE; e++) g_probs[token * NE + e] = acc[e] * inv;
    }
}

// ---------------------------------------------------------------------------
// 2) Exact top-K per (batch, expert)
// ---------------------------------------------------------------------------
__global__ void k_topk() {
    const int pair = blockIdx.x, b = pair >> 3, e = pair & 7;
    const int t = threadIdx.x;               // 1024
    __shared__ unsigned keys[SEQ];
    __shared__ int s_cnt;

    for (int s = t; s < SEQ; s += blockDim.x) {
        unsigned bits = __float_as_uint(g_probs[((size_t)b * SEQ + s) * NE + e]);
        keys[s] = (bits & 0x80000000u) ? ~bits : (bits | 0x80000000u);
    }
    __syncthreads();

    unsigned lo = 0u, hi = 0xFFFFFFFFu;
    while (lo < hi) {
        const unsigned mid = lo + ((hi - lo) >> 1) + 1u;
        if (t == 0) s_cnt = 0;
        __syncthreads();
        int c = 0;
        for (int s = t; s < SEQ; s += blockDim.x) c += (keys[s] >= mid);
#pragma unroll
        for (int o = 16; o > 0; o >>= 1) c += __shfl_down_sync(0xffffffffu, c, o);
        if ((t & 31) == 0 && c) atomicAdd(&s_cnt, c);
        __syncthreads();
        const int cnt = s_cnt;
        __syncthreads();
        if (cnt >= TOPK) lo = mid; else hi = mid - 1u;
    }
    const unsigned T = lo;

    if (t == 0) s_cnt = 0;
    __syncthreads();
    for (int s = t; s < SEQ; s += blockDim.x) {
        if (keys[s] > T) {
            const int p = atomicAdd(&s_cnt, 1);
            g_idx[pair * TOPK + p]  = s;
            g_gate[pair * TOPK + p] = g_probs[((size_t)b * SEQ + s) * NE + e];
        }
    }
    __syncthreads();
    for (int s = t; s < SEQ; s += blockDim.x) {
        if (keys[s] == T) {
            const int p = atomicAdd(&s_cnt, 1);
            if (p < TOPK) {
                g_idx[pair * TOPK + p]  = s;
                g_gate[pair * TOPK + p] = g_probs[((size_t)b * SEQ + s) * NE + e];
            }
        }
    }
}

// ---------------------------------------------------------------------------
// 3) Weight prep: RN-round fp32 -> fp16 (split per matrix for graph overlap)
// ---------------------------------------------------------------------------
__global__ void k_prep1(const float* __restrict__ w1) {
    const size_t i = (size_t)blockIdx.x * blockDim.x + threadIdx.x;
    const size_t N4 = (size_t)NE * DF * DM / 4;
    if (i >= N4) return;
    float4 a = ((const float4*)w1)[i];
    __half2 a0 = __floats2half2_rn(a.x, a.y);
    __half2 a1 = __floats2half2_rn(a.z, a.w);
    uint2 ua;
    ua.x = *reinterpret_cast<unsigned*>(&a0);
    ua.y = *reinterpret_cast<unsigned*>(&a1);
    ((uint2*)g_w1h)[i] = ua;
}
__global__ void k_prep2(const float* __restrict__ w2) {
    const size_t i = (size_t)blockIdx.x * blockDim.x + threadIdx.x;
    const size_t N4 = (size_t)NE * DF * DM / 4;
    if (i >= N4) return;
    float4 c = ((const float4*)w2)[i];
    __half2 c0 = __floats2half2_rn(c.x, c.y);
    __half2 c1 = __floats2half2_rn(c.z, c.w);
    uint2 uc;
    uc.x = *reinterpret_cast<unsigned*>(&c0);
    uc.y = *reinterpret_cast<unsigned*>(&c1);
    ((uint2*)g_w2h)[i] = uc;
}

// ---------------------------------------------------------------------------
// 4) fp16 mma.sync GEMM. CTA tile 128x128, 8 warps (4x2), warp tile 32x64,
//    K-slab 64, 3-stage cp.async, ldmatrix, SPAD=72 conflict-free.
//    Expert-major z (e = z>>2). G1 gathers A rows directly from g_x16 via
//    per-thread row pointers (token ids from g_idx, smem-staged once).
// ---------------------------------------------------------------------------
#define SPAD        72
#define A_BYTES     (128 * SPAD * 2)     // 18432
#define STAGE_BYTES (2 * A_BYTES)        // 36864
#define NSTAGE      3
#define SMEM_MMA    (NSTAGE * STAGE_BYTES + 1024)

template<int K, bool G1>
__global__ void __launch_bounds__(256, 2) k_mma(const __half* __restrict__ Aall,
                                                const __half* __restrict__ Ball,
                                                void* __restrict__ outp) {
    constexpr int NS = K / 64;
    extern __shared__ __align__(16) char smem[];
    const uint32_t sb = smem_u32(smem);
    int* rowTok = (int*)(smem + NSTAGE * STAGE_BYTES);

    const int tid  = threadIdx.x;
    const int wid  = tid >> 5, lane = tid & 31;
    const int wm   = wid >> 1, wn = wid & 1;
    const int g    = lane >> 2, tg = lane & 3;
    const int mi   = lane >> 3, r8 = lane & 7;

    // Expert-major ordering: adjacent z-slices share the expert weight slab.
    const int e = blockIdx.z >> 2, b = blockIdx.z & 3;
    const int pair = b * NE + e;
    const int mBase = blockIdx.y * 128;
    const int nBase = blockIdx.x * 128;

    const __half* Bbase = Ball + (size_t)e * DF * DM + (size_t)nBase * K;

    // Per-thread source pointers for the 4 loader chunks (fixed rows).
    const char* aPtr[4];
    const char* bPtr[4];
    if (G1) {
        if (tid < 128) rowTok[tid] = g_idx[pair * TOPK + mBase + tid];
        __syncthreads();
    }
#pragma unroll
    for (int i = 0; i < 4; i++) {
        const int id = tid + i * 256, row = id >> 3, c16 = id & 7;
        if (G1) {
            aPtr[i] = (const char*)(Aall + ((size_t)b * SEQ + rowTok[row]) * K) + c16 * 16;
        } else {
            aPtr[i] = (const char*)(Aall + ((size_t)pair * TOPK + mBase + row) * K) + c16 * 16;
        }
        bPtr[i] = (const char*)(Bbase + (size_t)row * K) + c16 * 16;
    }

    // ldmatrix per-thread relative byte offsets (within a stage)
    uint32_t aoff[2], boff[4];
#pragma unroll
    for (int mt = 0; mt < 2; mt++)
        aoff[mt] = ((wm * 32 + mt * 16 + (mi & 1) * 8 + r8) * SPAD + (mi >> 1) * 8) * 2;
#pragma unroll
    for (int np = 0; np < 4; np++)
        boff[np] = ((wn * 64 + np * 16 + (mi >> 1) * 8 + r8) * SPAD + (mi & 1) * 8) * 2;

    auto load_slab = [&](int slab, int buf) {
        const uint32_t sA = sb + buf * STAGE_BYTES;
        const uint32_t sB = sA + A_BYTES;
        const size_t kofs = (size_t)slab * 128;
#pragma unroll
        for (int i = 0; i < 4; i++) {
            const int id = tid + i * 256, row = id >> 3, c16 = id & 7;
            const uint32_t off = row * (SPAD * 2) + c16 * 16;
            CP16(sA + off, aPtr[i] + kofs);
            CP16(sB + off, bPtr[i] + kofs);
        }
    };

    float acc[2][8][4];
#pragma unroll
    for (int mt = 0; mt < 2; mt++)
#pragma unroll
        for (int nt = 0; nt < 8; nt++)
#pragma unroll
            for (int f = 0; f < 4; f++) acc[mt][nt][f] = 0.f;

    load_slab(0, 0); CP_COMMIT();
    load_slab(1, 1); CP_COMMIT();

#pragma unroll 1
    for (int s = 0; s < NS; s++) {
        asm volatile("cp.async.wait_group %0;" :: "n"(NSTAGE - 2) : "memory");
        __syncthreads();
        // Prefetch slab s+2 into the buffer consumed at slab s-1.
        if (s + 2 < NS) { load_slab(s + 2, (s + 2) % NSTAGE); }
        CP_COMMIT();

        const uint32_t sA = sb + (s % NSTAGE) * STAGE_BYTES;
        const uint32_t sB = sA + A_BYTES;
#pragma unroll
        for (int ks = 0; ks < 4; ks++) {
            const uint32_t kofs = ks * 32;       // 16 halves
            uint32_t af[2][4];
#pragma unroll
            for (int mt = 0; mt < 2; mt++)
                LDSM4(af[mt][0], af[mt][1], af[mt][2], af[mt][3], sA + aoff[mt] + kofs);
            uint32_t bf[8][2];
#pragma unroll
            for (int np = 0; np < 4; np++)
                LDSM4(bf[2 * np][0], bf[2 * np][1], bf[2 * np + 1][0], bf[2 * np + 1][1],
                      sB + boff[np] + kofs);
#pragma unroll
            for (int mt = 0; mt < 2; mt++)
#pragma unroll
                for (int nt = 0; nt < 8; nt++)
                    mma_f16(acc[mt][nt], af[mt], bf[nt]);
        }
    }

    // ---- epilogue ----
    if (G1) {
        __half* hout = (__half*)outp;
#pragma unroll
        for (int mt = 0; mt < 2; mt++) {
            const int r0 = mBase + wm * 32 + mt * 16 + g;
#pragma unroll
            for (int nt = 0; nt < 8; nt++) {
                const int col = nBase + wn * 64 + nt * 8 + 2 * tg;
                const float* a = acc[mt][nt];
                __half2 lo = __floats2half2_rn(a[0] / (1.f + __expf(-a[0])),
                                               a[1] / (1.f + __expf(-a[1])));
                __half2 hi = __floats2half2_rn(a[2] / (1.f + __expf(-a[2])),
                                               a[3] / (1.f + __expf(-a[3])));
                *(unsigned*)(hout + ((size_t)pair * TOPK + r0) * DF + col)     = *reinterpret_cast<unsigned*>(&lo);
                *(unsigned*)(hout + ((size_t)pair * TOPK + r0 + 8) * DF + col) = *reinterpret_cast<unsigned*>(&hi);
            }
        }
    } else {
        float* out = (float*)outp;
#pragma unroll
        for (int mt = 0; mt < 2; mt++) {
            const int m0 = mBase + wm * 32 + mt * 16 + g;
            const int tok0 = g_idx[pair * TOPK + m0];
            const int tok1 = g_idx[pair * TOPK + m0 + 8];
            const float g0 = g_gate[pair * TOPK + m0];
            const float g1 = g_gate[pair * TOPK + m0 + 8];
            float* d0 = out + ((size_t)b * SEQ + tok0) * DM;
            float* d1 = out + ((size_t)b * SEQ + tok1) * DM;
#pragma unroll
            for (int nt = 0; nt < 8; nt++) {
                const int col = nBase + wn * 64 + nt * 8 + 2 * tg;  // 8B-aligned
                const float* a = acc[mt][nt];
                red_add_v2(d0 + col, g0 * a[0], g0 * a[1]);
                red_add_v2(d1 + col, g1 * a[2], g1 * a[3]);
            }
        }
    }
}

// ---------------------------------------------------------------------------
// 5) Zero output (poisoned before timing)
// ---------------------------------------------------------------------------
__global__ void k_zero(float* __restrict__ out, int n4) {
    const int i = blockIdx.x * blockDim.x + threadIdx.x;
    if (i < n4) ((float4*)out)[i] = make_float4(0.f, 0.f, 0.f, 0.f);
}

// ---------------------------------------------------------------------------
extern "C" void kernel_launch(void* const* d_in, const int* in_sizes, int n_in,
                              void* d_out, int out_size) {
    const float* x      = (const float*)d_in[0];
    const float* choice = (const float*)d_in[1];
    const float* w1     = (const float*)d_in[2];
    const float* w2     = (const float*)d_in[3];
    float* out = (float*)d_out;

    // One-time setup (runs on the uncaptured correctness call; no device alloc).
    static cudaStream_t s1, s2;
    static cudaEvent_t ev0, ev1, ev2;
    static int inited = 0;
    if (!inited) {
        cudaFuncSetAttribute(k_mma<DM, true>,  cudaFuncAttributeMaxDynamicSharedMemorySize, SMEM_MMA);
        cudaFuncSetAttribute(k_mma<DF, false>, cudaFuncAttributeMaxDynamicSharedMemorySize, SMEM_MMA);
        cudaStreamCreateWithFlags(&s1, cudaStreamNonBlocking);
        cudaStreamCreateWithFlags(&s2, cudaStreamNonBlocking);
        cudaEventCreateWithFlags(&ev0, cudaEventDisableTiming);
        cudaEventCreateWithFlags(&ev1, cudaEventDisableTiming);
        cudaEventCreateWithFlags(&ev2, cudaEventDisableTiming);
        inited = 1;
    }

    __half* x16_p; cudaGetSymbolAddress((void**)&x16_p, g_x16);
    __half* h_p;   cudaGetSymbolAddress((void**)&h_p,   g_h16);
    __half* w1h_p; cudaGetSymbolAddress((void**)&w1h_p, g_w1h);
    __half* w2h_p; cudaGetSymbolAddress((void**)&w2h_p, g_w2h);

    const unsigned PREP_BLKS = (unsigned)(((size_t)NE * DF * DM / 4 + 255) / 256);
    const unsigned X16_BLKS  = (unsigned)(((size_t)BATCH * SEQ * DM / 4 + 255) / 256);
    const int n4 = BATCH * SEQ * DM / 4;

    // Fork side branches off the main stream.
    cudaEventRecord(ev0, 0);
    cudaStreamWaitEvent(s1, ev0, 0);
    cudaStreamWaitEvent(s2, ev0, 0);

    // Branch s1: w1 conversion (needed by GEMM1).
    k_prep1<<<PREP_BLKS, 256, 0, s1>>>(w1);
    cudaEventRecord(ev1, s1);

    // Branch s2: w2 conversion + output zeroing (needed by GEMM2).
    k_prep2<<<PREP_BLKS, 256, 0, s2>>>(w2);
    k_zero<<<(n4 + 255) / 256, 256, 0, s2>>>(out, n4);
    cudaEventRecord(ev2, s2);

    // Main branch: x->fp16, routing, topk.
    k_x16<<<X16_BLKS, 256>>>(x);
    k_route<<<(BATCH * SEQ) / 8, 256>>>(x, choice);
    k_topk<<<NPAIR, 1024>>>();

    // Join w1 branch, run GEMM1 (direct gather from g_x16): K=1024 per pair.
    cudaStreamWaitEvent(0, ev1, 0);
    k_mma<DM, true><<<dim3(DF / 128, TOPK / 128, NPAIR), 256, SMEM_MMA>>>(x16_p, w1h_p, h_p);

    // Join w2+zero branch, run GEMM2: [512 x 1024], K=4096 per pair.
    cudaStreamWaitEvent(0, ev2, 0);
    k_mma<DF, false><<<dim3(DM / 128, TOPK / 128, NPAIR), 256, SMEM_MMA>>>(h_p, w2h_p, out);
}